// round 12
// baseline (speedup 1.0000x reference)
#include <cuda_runtime.h>
#include <stdint.h>

// PicMix: output = two index-function masks, no input read.
// Flattened: [mask_a (8,12,512,512) fp32][mask_b same]. 192 planes of 512x512.
// group g = (ch%12)/3; isB = second mask.
//   g0: a=1,b=0 | g1: a=(i%2==j%2) | g2: a=i%2 | g3: a=j%2 ; b = complement.
// Each float4 covers j..j+3 (even start) -> lanes are (even,odd,even,odd).
//
// R12: final block-size axis — 512 threads/block (previously always 256),
// 4 float4/thread, 6144 CTAs. Same 64B/thread as the sweep optimum; fewer
// CTA wave transitions, no __syncthreads so larger blocks are free.
// Thread stride = 512 f4 = exactly 4 rows -> row parity still invariant
// per thread: decode once, 4x STG.E.128 at immediate offsets.
//
// Session evidence: 7 store mechanisms all plateau at 27.7-30.7us ncu /
// 58-65% DRAM = chip-wide path-independent LTS store ceiling (~7.2 TB/s
// L2-side). 201.3 MB mandatory output -> ~28us floor; this experiment only
// probes the last jitter-level scheduling term.

static constexpr int PLANE_F4         = 65536;  // 512*512/4
static constexpr int BLOCKS_PER_PLANE = 32;
static constexpr int F4_PER_BLOCK     = PLANE_F4 / BLOCKS_PER_PLANE; // 2048
static constexpr int THREADS          = 512;
static constexpr int F4_PER_THREAD    = F4_PER_BLOCK / THREADS;      // 4

__global__ void __launch_bounds__(THREADS) picmix_kernel(float4* __restrict__ out) {
    int plane = blockIdx.x >> 5;        // BLOCKS_PER_PLANE = 32
    int seg   = blockIdx.x & 31;

    int base = plane * PLANE_F4 + seg * F4_PER_BLOCK + threadIdx.x;
    int ip   = (base >> 7) & 1;         // row parity; stride 512 f4 = 4 rows -> invariant

    int isB = plane >= 96;              // 96 planes per mask
    int pin = isB ? plane - 96 : plane;
    int ch  = pin % 12;
    int g   = ch * 0x5556 >> 16;        // ch/3 for ch in [0,12)

    float e, o;                         // even-j value, odd-j value
    if (g == 0) {
        e = o = isB ? 0.0f : 1.0f;
    } else if (g == 1) {
        float s = (ip == 0) ? 1.0f : 0.0f;   // mask_a even lane
        e = isB ? 1.0f - s : s;
        o = 1.0f - e;
    } else if (g == 2) {
        float v = (float)ip;
        e = o = isB ? 1.0f - v : v;
    } else {
        e = isB ? 1.0f : 0.0f;
        o = 1.0f - e;
    }

    float4 v4 = make_float4(e, o, e, o);
    float4* p = out + base;
    #pragma unroll
    for (int k = 0; k < F4_PER_THREAD; k++) {
        p[k * THREADS] = v4;            // stride 512 f4 = 8KB = 4 rows
    }
}

extern "C" void kernel_launch(void* const* d_in, const int* in_sizes, int n_in,
                              void* d_out, int out_size) {
    (void)d_in; (void)in_sizes; (void)n_in; (void)out_size;
    // out_size = 50,331,648 fp32 = 192 planes * 65536 f4
    int blocks = 192 * BLOCKS_PER_PLANE;  // 6144
    picmix_kernel<<<blocks, THREADS>>>((float4*)d_out);
}